// round 3
// baseline (speedup 1.0000x reference)
#include <cuda_runtime.h>

#define NMAX 50000
#define EMAX 800000
#define DD   128

// ---------------- device scratch (no allocations allowed) ----------------
__device__ float g_hs[NMAX * DD];     // (x@W) * dinv[row]
__device__ float g_res[NMAX * DD];    // running residual
__device__ float g_dinv[NMAX];
__device__ int   g_deg[NMAX];
__device__ int   g_rowstart[NMAX + 1];
__device__ int   g_cursor[NMAX];
__device__ int   g_csrc[EMAX];
__device__ int   g_bsums[64];

// ---------------- degree / CSR build ----------------
__global__ void k_zero_deg(int n) {
    int i = blockIdx.x * blockDim.x + threadIdx.x;
    if (i < n) g_deg[i] = 0;
}

__global__ void k_count(const int* __restrict__ ei, int E) {
    int e = blockIdx.x * blockDim.x + threadIdx.x;
    if (e < E) {
        int d = ei[E + e];
        atomicAdd(&g_deg[d], 1);
    }
}

// block-wise inclusive scan (Hillis-Steele) over chunks of 1024
__global__ void k_scan1(int n) {
    __shared__ int sh[1024];
    int tid = threadIdx.x;
    int gid = blockIdx.x * 1024 + tid;
    int v = (gid < n) ? g_deg[gid] : 0;
    sh[tid] = v;
    __syncthreads();
    #pragma unroll
    for (int off = 1; off < 1024; off <<= 1) {
        int t = (tid >= off) ? sh[tid - off] : 0;
        __syncthreads();
        sh[tid] += t;
        __syncthreads();
    }
    if (gid < n) g_rowstart[gid + 1] = sh[tid];
    if (tid == 1023) g_bsums[blockIdx.x] = sh[1023];
}

__global__ void k_scan2(int nb) {
    if (threadIdx.x == 0 && blockIdx.x == 0) {
        int run = 0;
        for (int b = 0; b < nb; b++) {
            int t = g_bsums[b];
            g_bsums[b] = run;
            run += t;
        }
    }
}

__global__ void k_scan3(int n) {
    int gid = blockIdx.x * blockDim.x + threadIdx.x;
    if (gid < n) {
        int off  = g_bsums[gid >> 10];
        int incl = g_rowstart[gid + 1] + off;
        g_rowstart[gid + 1] = incl;
        int dg = g_deg[gid];
        g_cursor[gid] = incl - dg;              // exclusive start
        g_dinv[gid]   = rsqrtf((float)dg + 1.0f);
        if (gid == 0) g_rowstart[0] = 0;
    }
}

__global__ void k_scatter(const int* __restrict__ ei, int E) {
    int e = blockIdx.x * blockDim.x + threadIdx.x;
    if (e < E) {
        int d = ei[E + e];
        int s = ei[e];
        int p = atomicAdd(&g_cursor[d], 1);
        g_csrc[p] = s;
    }
}

// ---------------- GEMM: g_hs = (in @ W) * dinv[row] ----------------
// 64 rows per block, 256 threads, K tiled by 32.
// use_res != 0 -> input is g_res (ignore 'in' arg)
__global__ __launch_bounds__(256) void k_gemm_scale(
    const float* __restrict__ xin, const float* __restrict__ W, int n, int use_res)
{
    __shared__ float Wsh[32 * 128];   // [kk][c]
    __shared__ float xs[64 * 32];     // [r][kk]
    int tid  = threadIdx.x;
    int lane = tid & 31;
    int rbase = (tid >> 5) * 8;
    int row0 = blockIdx.x * 64;

    const float4* in4 = use_res ? (const float4*)g_res : (const float4*)xin;
    const float4* W4  = (const float4*)W;
    float4* Wsh4 = (float4*)Wsh;
    float4* xs4  = (float4*)xs;

    float4 acc[8];
    #pragma unroll
    for (int r = 0; r < 8; r++) acc[r] = make_float4(0.f, 0.f, 0.f, 0.f);

    for (int kt = 0; kt < 4; kt++) {
        // W rows [kt*32, kt*32+32): 1024 float4
        for (int i = tid; i < 1024; i += 256) Wsh4[i] = W4[kt * 1024 + i];
        // x tile [64 rows][32 k]: 512 float4
        for (int i = tid; i < 512; i += 256) {
            int r = i >> 3, c = i & 7;
            int gr = row0 + r;
            xs4[i] = (gr < n) ? in4[gr * 32 + kt * 8 + c]
                              : make_float4(0.f, 0.f, 0.f, 0.f);
        }
        __syncthreads();
        #pragma unroll 8
        for (int kk = 0; kk < 32; kk++) {
            float4 wv = Wsh4[kk * 32 + lane];
            #pragma unroll
            for (int r = 0; r < 8; r++) {
                float xv = xs[(rbase + r) * 32 + kk];
                acc[r].x += xv * wv.x;
                acc[r].y += xv * wv.y;
                acc[r].z += xv * wv.z;
                acc[r].w += xv * wv.w;
            }
        }
        __syncthreads();
    }

    float4* hs4 = (float4*)g_hs;
    #pragma unroll
    for (int r = 0; r < 8; r++) {
        int gr = row0 + rbase + r;
        if (gr < n) {
            float s = g_dinv[gr];
            float4 v = acc[r];
            v.x *= s; v.y *= s; v.z *= s; v.w *= s;
            hs4[gr * 32 + lane] = v;
        }
    }
}

// ---------------- fused aggregate + bias + LayerNorm + ReLU + residual ----
// one warp per destination node.
// mode: 0 = write g_res, no residual add
//       1 = g_res += result (residual), write g_res
//       2 = out = g_res + result (final layer)
__global__ __launch_bounds__(256) void k_agg_ln(
    const float* __restrict__ b, const float* __restrict__ gamma,
    const float* __restrict__ beta, float* __restrict__ out, int n, int mode)
{
    int warp = (blockIdx.x * blockDim.x + threadIdx.x) >> 5;
    if (warp >= n) return;
    int lane = threadIdx.x & 31;
    int i = warp;

    const float4* hs4 = (const float4*)g_hs;
    float4 acc = hs4[i * 32 + lane];           // self term (already dinv-scaled)

    int s0 = g_rowstart[i], s1 = g_rowstart[i + 1];
    int e = s0;
    for (; e + 4 <= s1; e += 4) {
        int sa = g_csrc[e], sb = g_csrc[e + 1], sc = g_csrc[e + 2], sd = g_csrc[e + 3];
        float4 va = hs4[sa * 32 + lane];
        float4 vb = hs4[sb * 32 + lane];
        float4 vc = hs4[sc * 32 + lane];
        float4 vd = hs4[sd * 32 + lane];
        acc.x += va.x + vb.x + vc.x + vd.x;
        acc.y += va.y + vb.y + vc.y + vd.y;
        acc.z += va.z + vb.z + vc.z + vd.z;
        acc.w += va.w + vb.w + vc.w + vd.w;
    }
    for (; e < s1; e++) {
        float4 v = hs4[g_csrc[e] * 32 + lane];
        acc.x += v.x; acc.y += v.y; acc.z += v.z; acc.w += v.w;
    }

    float di = g_dinv[i];
    float4 bb = ((const float4*)b)[lane];
    float4 v;
    v.x = acc.x * di + bb.x;
    v.y = acc.y * di + bb.y;
    v.z = acc.z * di + bb.z;
    v.w = acc.w * di + bb.w;

    // LayerNorm over 128 (4 per lane)
    float s = v.x + v.y + v.z + v.w;
    #pragma unroll
    for (int off = 16; off; off >>= 1) s += __shfl_xor_sync(0xFFFFFFFFu, s, off);
    float mu = s * (1.0f / 128.0f);
    float4 d;
    d.x = v.x - mu; d.y = v.y - mu; d.z = v.z - mu; d.w = v.w - mu;
    float sq = d.x * d.x + d.y * d.y + d.z * d.z + d.w * d.w;
    #pragma unroll
    for (int off = 16; off; off >>= 1) sq += __shfl_xor_sync(0xFFFFFFFFu, sq, off);
    float rs = rsqrtf(sq * (1.0f / 128.0f) + 1e-5f);

    float4 g4 = ((const float4*)gamma)[lane];
    float4 be = ((const float4*)beta)[lane];
    v.x = fmaxf(d.x * rs * g4.x + be.x, 0.f);
    v.y = fmaxf(d.y * rs * g4.y + be.y, 0.f);
    v.z = fmaxf(d.z * rs * g4.z + be.z, 0.f);
    v.w = fmaxf(d.w * rs * g4.w + be.w, 0.f);

    float4* res4 = (float4*)g_res;
    if (mode == 0) {
        res4[i * 32 + lane] = v;
    } else if (mode == 1) {
        float4 r = res4[i * 32 + lane];
        v.x += r.x; v.y += r.y; v.z += r.z; v.w += r.w;
        res4[i * 32 + lane] = v;
    } else {
        float4 r = res4[i * 32 + lane];
        v.x += r.x; v.y += r.y; v.z += r.z; v.w += r.w;
        ((float4*)out)[i * 32 + lane] = v;
    }
}

// ---------------- launch ----------------
extern "C" void kernel_launch(void* const* d_in, const int* in_sizes, int n_in,
                              void* d_out, int out_size) {
    const float* x      = (const float*)d_in[0];
    const int*   ei     = (const int*)d_in[1];     // int32: JAX demotes int64
    const float* Ws     = (const float*)d_in[2];
    const float* bs     = (const float*)d_in[3];
    const float* gammas = (const float*)d_in[4];
    const float* betas  = (const float*)d_in[5];
    float*       out    = (float*)d_out;

    int N = in_sizes[0] / DD;
    int E = in_sizes[1] / 2;

    int nb_nodes = (N + 255) / 256;
    int nb_edges = (E + 255) / 256;
    int nb_scan  = (N + 1023) / 1024;

    // degree + CSR build
    k_zero_deg<<<nb_nodes, 256>>>(N);
    k_count<<<nb_edges, 256>>>(ei, E);
    k_scan1<<<nb_scan, 1024>>>(N);
    k_scan2<<<1, 32>>>(nb_scan);
    k_scan3<<<nb_nodes, 256>>>(N);
    k_scatter<<<nb_edges, 256>>>(ei, E);

    int nb_gemm = (N + 63) / 64;
    int nb_agg  = (N * 32 + 255) / 256;

    // layer 0: res = LN(conv(x)) relu
    k_gemm_scale<<<nb_gemm, 256>>>(x, Ws + 0 * DD * DD, N, 0);
    k_agg_ln<<<nb_agg, 256>>>(bs + 0 * DD, gammas + 0 * DD, betas + 0 * DD, out, N, 0);
    // layer 1: res = res + LN(conv(res)) relu
    k_gemm_scale<<<nb_gemm, 256>>>(x, Ws + 1 * DD * DD, N, 1);
    k_agg_ln<<<nb_agg, 256>>>(bs + 1 * DD, gammas + 1 * DD, betas + 1 * DD, out, N, 1);
    // layer 2: out = res + LN(conv(res)) relu
    k_gemm_scale<<<nb_gemm, 256>>>(x, Ws + 2 * DD * DD, N, 1);
    k_agg_ln<<<nb_agg, 256>>>(bs + 2 * DD, gammas + 2 * DD, betas + 2 * DD, out, N, 2);
}

// round 5
// speedup vs baseline: 1.0997x; 1.0997x over previous
#include <cuda_runtime.h>

#define NMAX 50000
#define EMAX 800000
#define DD   128

// ---------------- device scratch (no allocations allowed) ----------------
__device__ float g_hs[NMAX * DD];     // (x@W) * dinv[row]
__device__ float g_res[NMAX * DD];    // running residual
__device__ float g_dinv[NMAX];
__device__ int   g_deg[NMAX];
__device__ int   g_rowstart[NMAX + 1];
__device__ int   g_cursor[NMAX];
__device__ int   g_csrc[EMAX];
__device__ int   g_bsums[64];

// ---------------- degree / CSR build ----------------
__global__ void k_zero_deg(int n) {
    int i = blockIdx.x * blockDim.x + threadIdx.x;
    if (i < n) g_deg[i] = 0;
}

__global__ void k_count(const int* __restrict__ ei, int E) {
    int e = blockIdx.x * blockDim.x + threadIdx.x;
    if (e < E) {
        int d = ei[E + e];
        atomicAdd(&g_deg[d], 1);
    }
}

// block-wise inclusive scan (Hillis-Steele) over chunks of 1024
__global__ void k_scan1(int n) {
    __shared__ int sh[1024];
    int tid = threadIdx.x;
    int gid = blockIdx.x * 1024 + tid;
    int v = (gid < n) ? g_deg[gid] : 0;
    sh[tid] = v;
    __syncthreads();
    #pragma unroll
    for (int off = 1; off < 1024; off <<= 1) {
        int t = (tid >= off) ? sh[tid - off] : 0;
        __syncthreads();
        sh[tid] += t;
        __syncthreads();
    }
    if (gid < n) g_rowstart[gid + 1] = sh[tid];
    if (tid == 1023) g_bsums[blockIdx.x] = sh[1023];
}

// parallel exclusive scan of block sums (nb <= 64), one warp
__global__ void k_scan2(int nb) {
    int t = threadIdx.x;              // 32 threads
    int v0 = (t < nb) ? g_bsums[t] : 0;
    int v1 = (t + 32 < nb) ? g_bsums[t + 32] : 0;
    int s0 = v0;
    #pragma unroll
    for (int o = 1; o < 32; o <<= 1) {
        int u = __shfl_up_sync(0xFFFFFFFFu, s0, o);
        if (t >= o) s0 += u;
    }
    int tot0 = __shfl_sync(0xFFFFFFFFu, s0, 31);
    int s1 = v1;
    #pragma unroll
    for (int o = 1; o < 32; o <<= 1) {
        int u = __shfl_up_sync(0xFFFFFFFFu, s1, o);
        if (t >= o) s1 += u;
    }
    s1 += tot0;
    if (t < nb)      g_bsums[t]      = s0 - v0;
    if (t + 32 < nb) g_bsums[t + 32] = s1 - v1;
}

__global__ void k_scan3(int n) {
    int gid = blockIdx.x * blockDim.x + threadIdx.x;
    if (gid < n) {
        int off  = g_bsums[gid >> 10];
        int incl = g_rowstart[gid + 1] + off;
        g_rowstart[gid + 1] = incl;
        int dg = g_deg[gid];
        g_cursor[gid] = incl - dg;              // exclusive start
        g_dinv[gid]   = rsqrtf((float)dg + 1.0f);
        if (gid == 0) g_rowstart[0] = 0;
    }
}

__global__ void k_scatter(const int* __restrict__ ei, int E) {
    int e = blockIdx.x * blockDim.x + threadIdx.x;
    if (e < E) {
        int d = ei[E + e];
        int s = ei[e];
        int p = atomicAdd(&g_cursor[d], 1);
        g_csrc[p] = s;
    }
}

// ---------------- TF32 helpers ----------------
__device__ __forceinline__ unsigned f2tf32(float f) {
    unsigned u;
    asm("cvt.rna.tf32.f32 %0, %1;" : "=r"(u) : "f"(f));
    return u;
}
__device__ __forceinline__ void split_tf32(float a, unsigned& hi, unsigned& lo) {
    hi = f2tf32(a);
    float hif = __uint_as_float(hi);
    lo = f2tf32(a - hif);
}
__device__ __forceinline__ void mma_tf32(float& c0, float& c1, float& c2, float& c3,
                                         unsigned a0, unsigned a1, unsigned a2, unsigned a3,
                                         unsigned b0, unsigned b1) {
    asm volatile(
        "mma.sync.aligned.m16n8k8.row.col.f32.tf32.tf32.f32 "
        "{%0,%1,%2,%3}, {%4,%5,%6,%7}, {%8,%9}, {%0,%1,%2,%3};\n"
        : "+f"(c0), "+f"(c1), "+f"(c2), "+f"(c3)
        : "r"(a0), "r"(a1), "r"(a2), "r"(a3), "r"(b0), "r"(b1));
}

// ---------------- GEMM: g_hs = (in @ W) * dinv[row], 3xTF32 tensor cores --
// block = 256 threads (8 warps), tile = 128 rows x 128 cols, K chunked by 32.
// warp w owns rows [128*blk + 16w, +16). use_res -> input is g_res.
#define XS_STRIDE 36
#define WS_STRIDE 136
__global__ __launch_bounds__(256) void k_gemm_tf32(
    const float* __restrict__ xin, const float* __restrict__ W, int n, int use_res)
{
    __shared__ float xs[128 * XS_STRIDE];   // [r][kk]  (pad 36: conflict-free A frags)
    __shared__ float Wsh[32 * WS_STRIDE];   // [kk][c]  (pad 136: conflict-free B frags)

    int tid  = threadIdx.x;
    int lane = tid & 31;
    int warp = tid >> 5;
    int row0 = blockIdx.x * 128;

    const float4* in4 = use_res ? (const float4*)g_res : (const float4*)xin;
    const float4* W4  = (const float4*)W;

    int g   = lane >> 2;     // groupID 0..7
    int tg  = lane & 3;      // thread-in-group 0..3

    float acc[16][4];
    #pragma unroll
    for (int nt = 0; nt < 16; nt++)
        #pragma unroll
        for (int j = 0; j < 4; j++) acc[nt][j] = 0.f;

    for (int kt = 0; kt < 4; kt++) {
        // W chunk rows [32kt, 32kt+32), 128 cols: 1024 float4
        #pragma unroll
        for (int i = tid; i < 1024; i += 256) {
            int kk = i >> 5, c4 = i & 31;
            *(float4*)&Wsh[kk * WS_STRIDE + c4 * 4] = W4[kt * 1024 + i];
        }
        // x tile: 128 rows x 32 k: 1024 float4  (FIX: was 512 -> half tile stale)
        #pragma unroll
        for (int i = tid; i < 1024; i += 256) {
            int r = i >> 3, c4 = i & 7;
            int gr = row0 + r;
            float4 v = (gr < n) ? in4[gr * 32 + kt * 8 + c4]
                                : make_float4(0.f, 0.f, 0.f, 0.f);
            *(float4*)&xs[r * XS_STRIDE + c4 * 4] = v;
        }
        __syncthreads();

        #pragma unroll
        for (int ks = 0; ks < 4; ks++) {
            int k0 = ks * 8;
            // A fragment (m16k8, row-major):
            // a0:(g, tg) a1:(g+8, tg) a2:(g, tg+4) a3:(g+8, tg+4)
            int ra = warp * 16 + g;
            float fa0 = xs[ra * XS_STRIDE + k0 + tg];
            float fa1 = xs[(ra + 8) * XS_STRIDE + k0 + tg];
            float fa2 = xs[ra * XS_STRIDE + k0 + tg + 4];
            float fa3 = xs[(ra + 8) * XS_STRIDE + k0 + tg + 4];
            unsigned ah0, al0, ah1, al1, ah2, al2, ah3, al3;
            split_tf32(fa0, ah0, al0);
            split_tf32(fa1, ah1, al1);
            split_tf32(fa2, ah2, al2);
            split_tf32(fa3, ah3, al3);

            #pragma unroll
            for (int nt = 0; nt < 16; nt++) {
                int n0 = nt * 8;
                // B fragment (k8n8, col-major): b0:(k=tg, n=g) b1:(k=tg+4, n=g)
                float fb0 = Wsh[(k0 + tg) * WS_STRIDE + n0 + g];
                float fb1 = Wsh[(k0 + tg + 4) * WS_STRIDE + n0 + g];
                unsigned bh0, bl0, bh1, bl1;
                split_tf32(fb0, bh0, bl0);
                split_tf32(fb1, bh1, bl1);

                mma_tf32(acc[nt][0], acc[nt][1], acc[nt][2], acc[nt][3],
                         ah0, ah1, ah2, ah3, bh0, bh1);
                mma_tf32(acc[nt][0], acc[nt][1], acc[nt][2], acc[nt][3],
                         ah0, ah1, ah2, ah3, bl0, bl1);
                mma_tf32(acc[nt][0], acc[nt][1], acc[nt][2], acc[nt][3],
                         al0, al1, al2, al3, bh0, bh1);
            }
        }
        __syncthreads();
    }

    // epilogue: scale by dinv[row], store.
    // C mapping m16n8: c0,c1 at (g, 2*tg+{0,1}); c2,c3 at (g+8, ...)
    int r_lo = row0 + warp * 16 + g;
    int r_hi = r_lo + 8;
    float d_lo = (r_lo < n) ? g_dinv[r_lo] : 0.f;
    float d_hi = (r_hi < n) ? g_dinv[r_hi] : 0.f;
    float2* hs2 = (float2*)g_hs;
    #pragma unroll
    for (int nt = 0; nt < 16; nt++) {
        int col = nt * 8 + tg * 2;
        if (r_lo < n) hs2[(r_lo * 128 + col) >> 1] =
            make_float2(acc[nt][0] * d_lo, acc[nt][1] * d_lo);
        if (r_hi < n) hs2[(r_hi * 128 + col) >> 1] =
            make_float2(acc[nt][2] * d_hi, acc[nt][3] * d_hi);
    }
}

// ---------------- fused aggregate + bias + LayerNorm + ReLU + residual ----
// one warp per destination node.
// mode: 0 = write g_res; 1 = g_res += result; 2 = out = g_res + result
__global__ __launch_bounds__(256) void k_agg_ln(
    const float* __restrict__ b, const float* __restrict__ gamma,
    const float* __restrict__ beta, float* __restrict__ out, int n, int mode)
{
    int warp = (blockIdx.x * blockDim.x + threadIdx.x) >> 5;
    if (warp >= n) return;
    int lane = threadIdx.x & 31;
    int i = warp;

    const float4* hs4 = (const float4*)g_hs;
    float4 acc = hs4[i * 32 + lane];           // self term (already dinv-scaled)

    int s0 = g_rowstart[i], s1 = g_rowstart[i + 1];
    int e = s0;
    for (; e + 4 <= s1; e += 4) {
        int sa = g_csrc[e], sb = g_csrc[e + 1], sc = g_csrc[e + 2], sd = g_csrc[e + 3];
        float4 va = hs4[sa * 32 + lane];
        float4 vb = hs4[sb * 32 + lane];
        float4 vc = hs4[sc * 32 + lane];
        float4 vd = hs4[sd * 32 + lane];
        acc.x += va.x + vb.x + vc.x + vd.x;
        acc.y += va.y + vb.y + vc.y + vd.y;
        acc.z += va.z + vb.z + vc.z + vd.z;
        acc.w += va.w + vb.w + vc.w + vd.w;
    }
    for (; e < s1; e++) {
        float4 v = hs4[g_csrc[e] * 32 + lane];
        acc.x += v.x; acc.y += v.y; acc.z += v.z; acc.w += v.w;
    }

    float di = g_dinv[i];
    float4 bb = ((const float4*)b)[lane];
    float4 v;
    v.x = acc.x * di + bb.x;
    v.y = acc.y * di + bb.y;
    v.z = acc.z * di + bb.z;
    v.w = acc.w * di + bb.w;

    // LayerNorm over 128 (4 per lane)
    float s = v.x + v.y + v.z + v.w;
    #pragma unroll
    for (int off = 16; off; off >>= 1) s += __shfl_xor_sync(0xFFFFFFFFu, s, off);
    float mu = s * (1.0f / 128.0f);
    float4 d;
    d.x = v.x - mu; d.y = v.y - mu; d.z = v.z - mu; d.w = v.w - mu;
    float sq = d.x * d.x + d.y * d.y + d.z * d.z + d.w * d.w;
    #pragma unroll
    for (int off = 16; off; off >>= 1) sq += __shfl_xor_sync(0xFFFFFFFFu, sq, off);
    float rs = rsqrtf(sq * (1.0f / 128.0f) + 1e-5f);

    float4 g4 = ((const float4*)gamma)[lane];
    float4 be = ((const float4*)beta)[lane];
    v.x = fmaxf(d.x * rs * g4.x + be.x, 0.f);
    v.y = fmaxf(d.y * rs * g4.y + be.y, 0.f);
    v.z = fmaxf(d.z * rs * g4.z + be.z, 0.f);
    v.w = fmaxf(d.w * rs * g4.w + be.w, 0.f);

    float4* res4 = (float4*)g_res;
    if (mode == 0) {
        res4[i * 32 + lane] = v;
    } else if (mode == 1) {
        float4 r = res4[i * 32 + lane];
        v.x += r.x; v.y += r.y; v.z += r.z; v.w += r.w;
        res4[i * 32 + lane] = v;
    } else {
        float4 r = res4[i * 32 + lane];
        v.x += r.x; v.y += r.y; v.z += r.z; v.w += r.w;
        ((float4*)out)[i * 32 + lane] = v;
    }
}

// ---------------- launch ----------------
extern "C" void kernel_launch(void* const* d_in, const int* in_sizes, int n_in,
                              void* d_out, int out_size) {
    const float* x      = (const float*)d_in[0];
    const int*   ei     = (const int*)d_in[1];     // int32 (JAX demotes int64)
    const float* Ws     = (const float*)d_in[2];
    const float* bs     = (const float*)d_in[3];
    const float* gammas = (const float*)d_in[4];
    const float* betas  = (const float*)d_in[5];
    float*       out    = (float*)d_out;

    int N = in_sizes[0] / DD;
    int E = in_sizes[1] / 2;

    int nb_nodes = (N + 255) / 256;
    int nb_edges = (E + 255) / 256;
    int nb_scan  = (N + 1023) / 1024;

    // degree + CSR build
    k_zero_deg<<<nb_nodes, 256>>>(N);
    k_count<<<nb_edges, 256>>>(ei, E);
    k_scan1<<<nb_scan, 1024>>>(N);
    k_scan2<<<1, 32>>>(nb_scan);
    k_scan3<<<nb_nodes, 256>>>(N);
    k_scatter<<<nb_edges, 256>>>(ei, E);

    int nb_gemm = (N + 127) / 128;
    int nb_agg  = (N * 32 + 255) / 256;

    // layer 0: res = LN(conv(x)) relu
    k_gemm_tf32<<<nb_gemm, 256>>>(x, Ws + 0 * DD * DD, N, 0);
    k_agg_ln<<<nb_agg, 256>>>(bs + 0 * DD, gammas + 0 * DD, betas + 0 * DD, out, N, 0);
    // layer 1: res = res + LN(conv(res)) relu
    k_gemm_tf32<<<nb_gemm, 256>>>(x, Ws + 1 * DD * DD, N, 1);
    k_agg_ln<<<nb_agg, 256>>>(bs + 1 * DD, gammas + 1 * DD, betas + 1 * DD, out, N, 1);
    // layer 2: out = res + LN(conv(res)) relu
    k_gemm_tf32<<<nb_gemm, 256>>>(x, Ws + 2 * DD * DD, N, 1);
    k_agg_ln<<<nb_agg, 256>>>(bs + 2 * DD, gammas + 2 * DD, betas + 2 * DD, out, N, 2);
}

// round 6
// speedup vs baseline: 1.1108x; 1.0101x over previous
#include <cuda_runtime.h>

#define NMAX 50000
#define EMAX 800000
#define DD   128

// ---------------- device scratch (no allocations allowed) ----------------
__device__ float g_hs[NMAX * DD];       // (x@W) * dinv[row]
__device__ float g_res[NMAX * DD];      // running residual
__device__ float g_dinv[NMAX];
__device__ int   g_deg[NMAX];
__device__ int   g_rowstart[NMAX + 1];
__device__ int   g_cursor[NMAX];
__device__ int   g_csrc[EMAX];
__device__ int   g_bsums[64];
__device__ uint2 g_wsplit[3 * DD * DD]; // per-layer W split into (tf32 hi, tf32 lo)

// ---------------- TF32 helpers ----------------
__device__ __forceinline__ unsigned f2tf32(float f) {
    unsigned u;
    asm("cvt.rna.tf32.f32 %0, %1;" : "=r"(u) : "f"(f));
    return u;
}
__device__ __forceinline__ void split_tf32(float a, unsigned& hi, unsigned& lo) {
    hi = f2tf32(a);
    float hif = __uint_as_float(hi);
    lo = f2tf32(a - hif);
}
__device__ __forceinline__ void mma_tf32(float* c,
                                         unsigned a0, unsigned a1, unsigned a2, unsigned a3,
                                         unsigned b0, unsigned b1) {
    asm volatile(
        "mma.sync.aligned.m16n8k8.row.col.f32.tf32.tf32.f32 "
        "{%0,%1,%2,%3}, {%4,%5,%6,%7}, {%8,%9}, {%0,%1,%2,%3};\n"
        : "+f"(c[0]), "+f"(c[1]), "+f"(c[2]), "+f"(c[3])
        : "r"(a0), "r"(a1), "r"(a2), "r"(a3), "r"(b0), "r"(b1));
}

// ---------------- W pre-split ----------------
__global__ void k_splitW(const float* __restrict__ Ws) {
    int i = blockIdx.x * blockDim.x + threadIdx.x;
    if (i < 3 * DD * DD) {
        float w = Ws[i];
        unsigned hi, lo;
        split_tf32(w, hi, lo);
        g_wsplit[i] = make_uint2(hi, lo);
    }
}

// ---------------- degree / CSR build ----------------
__global__ void k_zero_deg(int n) {
    int i = blockIdx.x * blockDim.x + threadIdx.x;
    if (i < n) g_deg[i] = 0;
}

__global__ void k_count(const int* __restrict__ ei, int E) {
    int e = blockIdx.x * blockDim.x + threadIdx.x;
    if (e < E) atomicAdd(&g_deg[ei[E + e]], 1);
}

// block-wise inclusive scan over chunks of 1024
__global__ void k_scan1(int n) {
    __shared__ int sh[1024];
    int tid = threadIdx.x;
    int gid = blockIdx.x * 1024 + tid;
    int v = (gid < n) ? g_deg[gid] : 0;
    sh[tid] = v;
    __syncthreads();
    #pragma unroll
    for (int off = 1; off < 1024; off <<= 1) {
        int t = (tid >= off) ? sh[tid - off] : 0;
        __syncthreads();
        sh[tid] += t;
        __syncthreads();
    }
    if (gid < n) g_rowstart[gid + 1] = sh[tid];
    if (tid == 1023) g_bsums[blockIdx.x] = sh[1023];
}

// fused: per-block recompute of bsums prefix (<=64 chunks) + finalize
// block = 256 threads; 256 divides 1024 so whole block is in one chunk.
__global__ void k_scan23(int n) {
    __shared__ int pref;
    int chunk = blockIdx.x >> 2;          // (blockIdx.x*256)/1024
    if (threadIdx.x < 32) {
        int t = threadIdx.x;
        int v = (t < chunk) ? g_bsums[t] : 0;
        if (t + 32 < chunk) v += g_bsums[t + 32];
        #pragma unroll
        for (int off = 16; off; off >>= 1) v += __shfl_xor_sync(0xFFFFFFFFu, v, off);
        if (t == 0) pref = v;
    }
    __syncthreads();
    int gid = blockIdx.x * 256 + threadIdx.x;
    if (gid < n) {
        int incl = g_rowstart[gid + 1] + pref;
        g_rowstart[gid + 1] = incl;
        int dg = g_deg[gid];
        g_cursor[gid] = incl - dg;
        g_dinv[gid]   = rsqrtf((float)dg + 1.0f);
        if (gid == 0) g_rowstart[0] = 0;
    }
}

__global__ void k_scatter(const int* __restrict__ ei, int E) {
    int e = blockIdx.x * blockDim.x + threadIdx.x;
    if (e < E) {
        int d = ei[E + e];
        int s = ei[e];
        int p = atomicAdd(&g_cursor[d], 1);
        g_csrc[p] = s;
    }
}

// ---------------- GEMM: g_hs = (in @ W) * dinv[row], 3xTF32 ----------------
// 128 threads (4 warps), tile 128 rows x 128 cols, warp owns 32 rows
// (two m16 groups). W pre-split; B frag = one LDS.64 (hi,lo) pair.
#define XS_STRIDE 36
#define WS2_STRIDE 132
__global__ __launch_bounds__(128, 2) void k_gemm_tf32(
    const float* __restrict__ xin, int layer, int n, int use_res)
{
    __shared__ float xs[128 * XS_STRIDE];     // [r][kk]
    __shared__ uint2 Wsh[32 * WS2_STRIDE];    // [kk][c] (hi,lo)

    int tid  = threadIdx.x;
    int lane = tid & 31;
    int warp = tid >> 5;
    int row0 = blockIdx.x * 128;

    const float4* in4 = use_res ? (const float4*)g_res : (const float4*)xin;
    const uint2*  Wg  = g_wsplit + layer * DD * DD;

    int g  = lane >> 2;
    int tg = lane & 3;

    float acc[2][16][4];
    #pragma unroll
    for (int gr2 = 0; gr2 < 2; gr2++)
        #pragma unroll
        for (int nt = 0; nt < 16; nt++)
            #pragma unroll
            for (int j = 0; j < 4; j++) acc[gr2][nt][j] = 0.f;

    for (int kt = 0; kt < 4; kt++) {
        // stage W chunk: 32 rows x 128 uint2 = 2048 uint4
        const uint4* Wg4 = (const uint4*)(Wg + kt * 32 * DD);
        #pragma unroll
        for (int i = tid; i < 2048; i += 128) {
            int kk = i >> 6, c2 = i & 63;
            *(uint4*)&Wsh[kk * WS2_STRIDE + c2 * 2] = Wg4[i];
        }
        // stage x tile: 128 rows x 8 float4
        #pragma unroll
        for (int i = tid; i < 1024; i += 128) {
            int r = i >> 3, c4 = i & 7;
            int gr = row0 + r;
            float4 v = (gr < n) ? in4[gr * 32 + kt * 8 + c4]
                                : make_float4(0.f, 0.f, 0.f, 0.f);
            *(float4*)&xs[r * XS_STRIDE + c4 * 4] = v;
        }
        __syncthreads();

        #pragma unroll
        for (int ks = 0; ks < 4; ks++) {
            int k0 = ks * 8;
            unsigned ah[2][4], al[2][4];
            #pragma unroll
            for (int gr2 = 0; gr2 < 2; gr2++) {
                int ra = warp * 32 + gr2 * 16 + g;
                float fa0 = xs[ra * XS_STRIDE + k0 + tg];
                float fa1 = xs[(ra + 8) * XS_STRIDE + k0 + tg];
                float fa2 = xs[ra * XS_STRIDE + k0 + tg + 4];
                float fa3 = xs[(ra + 8) * XS_STRIDE + k0 + tg + 4];
                split_tf32(fa0, ah[gr2][0], al[gr2][0]);
                split_tf32(fa1, ah[gr2][1], al[gr2][1]);
                split_tf32(fa2, ah[gr2][2], al[gr2][2]);
                split_tf32(fa3, ah[gr2][3], al[gr2][3]);
            }
            #pragma unroll
            for (int nt = 0; nt < 16; nt++) {
                int n0 = nt * 8;
                uint2 b0 = Wsh[(k0 + tg) * WS2_STRIDE + n0 + g];
                uint2 b1 = Wsh[(k0 + tg + 4) * WS2_STRIDE + n0 + g];
                #pragma unroll
                for (int gr2 = 0; gr2 < 2; gr2++) {
                    mma_tf32(acc[gr2][nt], ah[gr2][0], ah[gr2][1], ah[gr2][2], ah[gr2][3], b0.x, b1.x);
                    mma_tf32(acc[gr2][nt], ah[gr2][0], ah[gr2][1], ah[gr2][2], ah[gr2][3], b0.y, b1.y);
                    mma_tf32(acc[gr2][nt], al[gr2][0], al[gr2][1], al[gr2][2], al[gr2][3], b0.x, b1.x);
                }
            }
        }
        __syncthreads();
    }

    // epilogue: scale by dinv[row], store
    float2* hs2 = (float2*)g_hs;
    #pragma unroll
    for (int gr2 = 0; gr2 < 2; gr2++) {
        int r_lo = row0 + warp * 32 + gr2 * 16 + g;
        int r_hi = r_lo + 8;
        float d_lo = (r_lo < n) ? g_dinv[r_lo] : 0.f;
        float d_hi = (r_hi < n) ? g_dinv[r_hi] : 0.f;
        #pragma unroll
        for (int nt = 0; nt < 16; nt++) {
            int col = nt * 8 + tg * 2;
            if (r_lo < n) hs2[(r_lo * 128 + col) >> 1] =
                make_float2(acc[gr2][nt][0] * d_lo, acc[gr2][nt][1] * d_lo);
            if (r_hi < n) hs2[(r_hi * 128 + col) >> 1] =
                make_float2(acc[gr2][nt][2] * d_hi, acc[gr2][nt][3] * d_hi);
        }
    }
}

// ---------------- fused aggregate + bias + LayerNorm + ReLU + residual ----
// one warp per destination node.
// mode: 0 = write g_res; 1 = g_res += result; 2 = out = g_res + result
__global__ __launch_bounds__(256) void k_agg_ln(
    const float* __restrict__ b, const float* __restrict__ gamma,
    const float* __restrict__ beta, float* __restrict__ out, int n, int mode)
{
    int warp = (blockIdx.x * blockDim.x + threadIdx.x) >> 5;
    if (warp >= n) return;
    int lane = threadIdx.x & 31;
    int i = warp;

    const float4* hs4 = (const float4*)g_hs;
    float4 acc = hs4[i * 32 + lane];           // self term (already dinv-scaled)

    int s0 = g_rowstart[i], s1 = g_rowstart[i + 1];
    int e = s0;
    for (; e + 4 <= s1; e += 4) {
        int sa = g_csrc[e], sb = g_csrc[e + 1], sc = g_csrc[e + 2], sd = g_csrc[e + 3];
        float4 va = hs4[sa * 32 + lane];
        float4 vb = hs4[sb * 32 + lane];
        float4 vc = hs4[sc * 32 + lane];
        float4 vd = hs4[sd * 32 + lane];
        acc.x += va.x + vb.x + vc.x + vd.x;
        acc.y += va.y + vb.y + vc.y + vd.y;
        acc.z += va.z + vb.z + vc.z + vd.z;
        acc.w += va.w + vb.w + vc.w + vd.w;
    }
    for (; e < s1; e++) {
        float4 v = hs4[g_csrc[e] * 32 + lane];
        acc.x += v.x; acc.y += v.y; acc.z += v.z; acc.w += v.w;
    }

    float di = g_dinv[i];
    float4 bb = ((const float4*)b)[lane];
    float4 v;
    v.x = acc.x * di + bb.x;
    v.y = acc.y * di + bb.y;
    v.z = acc.z * di + bb.z;
    v.w = acc.w * di + bb.w;

    float s = v.x + v.y + v.z + v.w;
    #pragma unroll
    for (int off = 16; off; off >>= 1) s += __shfl_xor_sync(0xFFFFFFFFu, s, off);
    float mu = s * (1.0f / 128.0f);
    float4 d;
    d.x = v.x - mu; d.y = v.y - mu; d.z = v.z - mu; d.w = v.w - mu;
    float sq = d.x * d.x + d.y * d.y + d.z * d.z + d.w * d.w;
    #pragma unroll
    for (int off = 16; off; off >>= 1) sq += __shfl_xor_sync(0xFFFFFFFFu, sq, off);
    float rs = rsqrtf(sq * (1.0f / 128.0f) + 1e-5f);

    float4 g4 = ((const float4*)gamma)[lane];
    float4 be = ((const float4*)beta)[lane];
    v.x = fmaxf(d.x * rs * g4.x + be.x, 0.f);
    v.y = fmaxf(d.y * rs * g4.y + be.y, 0.f);
    v.z = fmaxf(d.z * rs * g4.z + be.z, 0.f);
    v.w = fmaxf(d.w * rs * g4.w + be.w, 0.f);

    float4* res4 = (float4*)g_res;
    if (mode == 0) {
        res4[i * 32 + lane] = v;
    } else if (mode == 1) {
        float4 r = res4[i * 32 + lane];
        v.x += r.x; v.y += r.y; v.z += r.z; v.w += r.w;
        res4[i * 32 + lane] = v;
    } else {
        float4 r = res4[i * 32 + lane];
        v.x += r.x; v.y += r.y; v.z += r.z; v.w += r.w;
        ((float4*)out)[i * 32 + lane] = v;
    }
}

// ---------------- launch ----------------
extern "C" void kernel_launch(void* const* d_in, const int* in_sizes, int n_in,
                              void* d_out, int out_size) {
    const float* x      = (const float*)d_in[0];
    const int*   ei     = (const int*)d_in[1];     // int32 (JAX demotes int64)
    const float* Ws     = (const float*)d_in[2];
    const float* bs     = (const float*)d_in[3];
    const float* gammas = (const float*)d_in[4];
    const float* betas  = (const float*)d_in[5];
    float*       out    = (float*)d_out;

    int N = in_sizes[0] / DD;
    int E = in_sizes[1] / 2;

    int nb_nodes = (N + 255) / 256;
    int nb_edges = (E + 255) / 256;
    int nb_scan  = (N + 1023) / 1024;

    k_splitW<<<(3 * DD * DD + 255) / 256, 256>>>(Ws);
    k_zero_deg<<<nb_nodes, 256>>>(N);
    k_count<<<nb_edges, 256>>>(ei, E);
    k_scan1<<<nb_scan, 1024>>>(N);
    k_scan23<<<nb_nodes, 256>>>(N);
    k_scatter<<<nb_edges, 256>>>(ei, E);

    int nb_gemm = (N + 127) / 128;
    int nb_agg  = (N * 32 + 255) / 256;

    k_gemm_tf32<<<nb_gemm, 128>>>(x, 0, N, 0);
    k_agg_ln<<<nb_agg, 256>>>(bs + 0 * DD, gammas + 0 * DD, betas + 0 * DD, out, N, 0);
    k_gemm_tf32<<<nb_gemm, 128>>>(x, 1, N, 1);
    k_agg_ln<<<nb_agg, 256>>>(bs + 1 * DD, gammas + 1 * DD, betas + 1 * DD, out, N, 1);
    k_gemm_tf32<<<nb_gemm, 128>>>(x, 2, N, 1);
    k_agg_ln<<<nb_agg, 256>>>(bs + 2 * DD, gammas + 2 * DD, betas + 2 * DD, out, N, 2);
}